// round 15
// baseline (speedup 1.0000x reference)
#include <cuda_runtime.h>
#include <cuda_fp16.h>
#include <cstdint>
#include <cstddef>

#define N_NODES 100000
#define M_PAD   100096            // 391 * 256
#define N_EDGES 3200000
#define DIM 512

// ---------------- scratch (device globals; no runtime allocation) ----------
__device__ __half g_x16[(size_t)M_PAD * DIM];    // fp16(x)
__device__ __half g_o16[(size_t)M_PAD * DIM];    // gemm outputs (both layers)
__device__ __half g_h16[(size_t)M_PAD * DIM];    // spmm1 output (gemm2 input); pad rows stay 0
__device__ __half g_w1t[DIM * DIM];
__device__ __half g_w2t[DIM * DIM];
__device__ int   g_row_ptr[N_NODES + 1];
__device__ int   g_counts[N_NODES];
__device__ int   g_srcs[N_EDGES];
__device__ float g_vals[N_EDGES];

// ---------------- PTX helpers ----------------------------------------------
__device__ __forceinline__ uint32_t smem_u32(const void* p) {
    uint32_t a;
    asm("{ .reg .u64 t; cvta.to.shared.u64 t, %1; cvt.u32.u64 %0, t; }" : "=r"(a) : "l"(p));
    return a;
}

#define CP_ASYNC16(smaddr, gptr) \
    asm volatile("cp.async.cg.shared.global [%0], [%1], 16;" :: "r"(smaddr), "l"(gptr))
#define CP_COMMIT() asm volatile("cp.async.commit_group;" ::: "memory")
#define CP_WAIT(N)  asm volatile("cp.async.wait_group %0;" :: "n"(N) : "memory")

#define LDSM4(R0, R1, R2, R3, addr) \
    asm volatile("ldmatrix.sync.aligned.m8n8.x4.shared.b16 {%0,%1,%2,%3}, [%4];" \
                 : "=r"(R0), "=r"(R1), "=r"(R2), "=r"(R3) : "r"(addr))

#define MMA16816F(C, A, B0, B1) \
    asm volatile("mma.sync.aligned.m16n8k16.row.col.f32.f16.f16.f32 " \
                 "{%0,%1,%2,%3}, {%4,%5,%6,%7}, {%8,%9}, {%0,%1,%2,%3};" \
                 : "+f"((C)[0]), "+f"((C)[1]), "+f"((C)[2]), "+f"((C)[3]) \
                 : "r"((A)[0]), "r"((A)[1]), "r"((A)[2]), "r"((A)[3]), \
                   "r"(B0), "r"(B1))

// ---------------- CSR pieces ------------------------------------------------
__global__ void zero_counts_kernel() {
    int i = blockIdx.x * blockDim.x + threadIdx.x;
    if (i < N_NODES) g_counts[i] = 0;
}

__global__ __launch_bounds__(1024) void scan_kernel() {
    __shared__ int partials[1024];
    int tid = threadIdx.x;
    const int CHUNK = (N_NODES + 1023) / 1024;
    int b = tid * CHUNK;
    int e = b + CHUNK; if (e > N_NODES) e = N_NODES;
    if (b > N_NODES) b = N_NODES;
    int sum = 0;
    for (int i = b; i < e; i++) sum += g_counts[i];
    partials[tid] = sum;
    __syncthreads();
    for (int off = 1; off < 1024; off <<= 1) {
        int t = (tid >= off) ? partials[tid - off] : 0;
        __syncthreads();
        partials[tid] += t;
        __syncthreads();
    }
    int run = partials[tid] - sum;
    for (int i = b; i < e; i++) {
        g_row_ptr[i] = run;
        run += g_counts[i];
        g_counts[i] = 0;
    }
    if (tid == 1023) g_row_ptr[N_NODES] = partials[1023];
}

// ---------------- merged prep: convert_x || hist || W transposes -------------
#define NB_CONV 12512     // 12512 blocks * 1024 float4 = M_PAD*DIM/4
#define NB_HIST 1568
#define NB_W    1024      // 1024 blocks * 256 = DIM*DIM
#define NB_PREP (NB_CONV + NB_HIST + 2 * NB_W)

__global__ __launch_bounds__(256) void prep_kernel(
    const float* __restrict__ x, const int* __restrict__ dst,
    const float* __restrict__ W1, const float* __restrict__ W2)
{
    int b = blockIdx.x;
    if (b < NB_CONV) {
#pragma unroll
        for (int j = 0; j < 4; j++) {
            size_t i = (size_t)b * 1024 + j * 256 + threadIdx.x;
            size_t row = i / (DIM / 4);
            float4 v = make_float4(0.f, 0.f, 0.f, 0.f);
            if (row < N_NODES) v = ((const float4*)x)[i];
            __half2 h0 = __floats2half2_rn(v.x, v.y);
            __half2 h1 = __floats2half2_rn(v.z, v.w);
            uint2 pk;
            pk.x = *(uint32_t*)&h0;
            pk.y = *(uint32_t*)&h1;
            ((uint2*)g_x16)[i] = pk;
        }
    } else if (b < NB_CONV + NB_HIST) {
        int gtid = (b - NB_CONV) * 256 + threadIdx.x;
        const int stride = NB_HIST * 256;
        for (int e = gtid; e < N_EDGES; e += stride)
            atomicAdd(&g_counts[__ldcs(dst + e)], 1);
    } else {
        int b3 = b - NB_CONV - NB_HIST;
        const float* W = (b3 < NB_W) ? W1 : W2;
        __half* Wt = (b3 < NB_W) ? g_w1t : g_w2t;
        int idx = (b3 & (NB_W - 1)) * 256 + threadIdx.x;
        int k = idx >> 9, n = idx & 511;
        Wt[n * DIM + k] = __float2half_rn(W[idx]);
    }
}

// ---------------- HMMA fp16 GEMM: 256x128 CTA tile, 512 thr, 3-stage ---------
// C[.,512](fp16) = A(fp16) @ Wt^T + bias, fp32 accum.
// 16 warps, warp tile 64x32, K-chunk 32, single-sync loop.
// Leading extraY block-rows perform the CSR scatter (gemm1 only).
#define BK 32
#define ROWB 80
#define OFF_B   20480                // A: 256 rows * 80B
#define STAGE_BYTES 30720            // + B: 128 rows * 80B
#define NSTAGE 3
#define GEMM_SMEM (NSTAGE * STAGE_BYTES)
#define NIT (DIM / BK)               // 16
#define SCAT_Y 32                    // 32*4 blocks * 512 thr = 65536 scatter threads

__device__ __forceinline__ void stage_load(
    uint32_t sbase, int stage,
    const __half* __restrict__ A, const __half* __restrict__ B,
    int m0, int n0, int k0, int tid)
{
    uint32_t s0 = sbase + (uint32_t)stage * STAGE_BYTES;
#pragma unroll
    for (int i = tid; i < 1536; i += 512) {
        int r = i >> 2, s = i & 3;
        if (r < 256) {
            uint32_t so = (uint32_t)r * ROWB + (uint32_t)s * 16u;
            const char* ga = (const char*)(A + (size_t)(m0 + r) * DIM + k0) + s * 16;
            CP_ASYNC16(s0 + so, ga);
        } else {
            int rb = r - 256;
            uint32_t so = OFF_B + (uint32_t)rb * ROWB + (uint32_t)s * 16u;
            const char* gb = (const char*)(B + (size_t)(n0 + rb) * DIM + k0) + s * 16;
            CP_ASYNC16(s0 + so, gb);
        }
    }
}

__global__ __launch_bounds__(512, 1) void gemm_f16_kernel(
    const __half* __restrict__ A, const __half* __restrict__ B,
    const float* __restrict__ bias, __half* __restrict__ C,
    int extraY,
    const int* __restrict__ esrc, const int* __restrict__ edst,
    const float* __restrict__ eval)
{
    if ((int)blockIdx.y < extraY) {
        // CSR scatter, grid-strided; overlaps with gemm tensor work
        int t0 = blockIdx.y * gridDim.x + blockIdx.x;          // 0..127
        int gtid = t0 * 512 + threadIdx.x;
        const int stride = SCAT_Y * 4 * 512;                   // 65536
        for (int e = gtid; e < N_EDGES; e += stride) {
            int d = __ldcs(edst + e);
            int pos = g_row_ptr[d] + atomicAdd(&g_counts[d], 1);
            g_srcs[pos] = __ldcs(esrc + e);
            g_vals[pos] = __ldcs(eval + e);
        }
        return;
    }

    extern __shared__ char sm[];
    const uint32_t sbase = smem_u32(sm);
    const int tid  = threadIdx.x;
    const int warp = tid >> 5;
    const int lane = tid & 31;
    const int wm = warp & 3;              // 0..3 -> M offset *64
    const int wn = warp >> 2;             // 0..3 -> N offset *32
    const int n0 = blockIdx.x * 128;      // n fastest -> wave shares A rows
    const int m0 = (blockIdx.y - extraY) * 256;

    float acc[4][4][4];
#pragma unroll
    for (int a = 0; a < 4; a++)
#pragma unroll
        for (int b = 0; b < 4; b++)
#pragma unroll
            for (int c = 0; c < 4; c++) acc[a][b][c] = 0.f;

    const int a_row = lane & 15;
    const int a_koff = (lane >> 4) * 8;
    const int b_g = lane >> 3;
    const int b_nloc = ((b_g >> 1) << 3) + (lane & 7);
    const int b_koff = (b_g & 1) * 8;

    // prime stages 0 and 1
    stage_load(sbase, 0, A, B, m0, n0, 0, tid);
    CP_COMMIT();
    stage_load(sbase, 1, A, B, m0, n0, BK, tid);
    CP_COMMIT();

    int stg = 0;
    for (int it = 0; it < NIT; ++it) {
        if (it + 1 < NIT) { CP_WAIT(1); } else { CP_WAIT(0); }
        __syncthreads();          // stage `stg` ready; all warps done with stage (stg+2)%3

        if (it + 2 < NIT) {
            int nstg = stg + 2; if (nstg >= NSTAGE) nstg -= NSTAGE;
            stage_load(sbase, nstg, A, B, m0, n0, (it + 2) * BK, tid);
            CP_COMMIT();
        }

        const uint32_t st = sbase + (uint32_t)stg * STAGE_BYTES;
#pragma unroll
        for (int kk = 0; kk < 2; ++kk) {
            const int k16 = kk * 16;
            uint32_t av[4][4];
#pragma unroll
            for (int mi = 0; mi < 4; ++mi) {
                uint32_t ra = (uint32_t)(wm * 64 + mi * 16 + a_row) * ROWB
                            + (uint32_t)(k16 + a_koff) * 2;
                LDSM4(av[mi][0], av[mi][1], av[mi][2], av[mi][3], st + ra);
            }
            uint32_t bv[2][4];
#pragma unroll
            for (int nb = 0; nb < 2; ++nb) {
                uint32_t rb = OFF_B + (uint32_t)(wn * 32 + nb * 16 + b_nloc) * ROWB
                            + (uint32_t)(k16 + b_koff) * 2;
                LDSM4(bv[nb][0], bv[nb][1], bv[nb][2], bv[nb][3], st + rb);
            }
#pragma unroll
            for (int mi = 0; mi < 4; ++mi) {
#pragma unroll
                for (int j = 0; j < 4; ++j) {
                    const int nb = j >> 1, blk = j & 1;
                    MMA16816F(acc[mi][j], av[mi], bv[nb][blk * 2], bv[nb][blk * 2 + 1]);
                }
            }
        }
        if (++stg >= NSTAGE) stg = 0;
    }

    // epilogue: bias add + fp16 store (plain stores -> lands in L2 for SpMM)
#pragma unroll
    for (int mi = 0; mi < 4; ++mi) {
        int row = m0 + wm * 64 + mi * 16 + (lane >> 2);
#pragma unroll
        for (int j = 0; j < 4; ++j) {
            int col = n0 + wn * 32 + j * 8 + (lane & 3) * 2;
            float b0 = bias[col], b1 = bias[col + 1];
            __half2 v0 = __floats2half2_rn(acc[mi][j][0] + b0, acc[mi][j][1] + b1);
            __half2 v1 = __floats2half2_rn(acc[mi][j][2] + b0, acc[mi][j][3] + b1);
            *(__half2*)(C + (size_t)row * DIM + col) = v0;
            *(__half2*)(C + (size_t)(row + 8) * DIM + col) = v1;
        }
    }
}

// ---------------- SpMM (CSR by dst), fp16 gather, one warp per row -----------
struct Acc16 { float2 f[8]; };

__device__ __forceinline__ void gather_row_h(const __half* __restrict__ H,
                                             int beg, int end, int lane, Acc16& A) {
#pragma unroll
    for (int j = 0; j < 8; j++) A.f[j] = make_float2(0.f, 0.f);
    for (int base = beg; base < end; base += 32) {
        int cnt = end - base; if (cnt > 32) cnt = 32;
        int s = 0; float v = 0.f;
        if (lane < cnt) { s = __ldcs(g_srcs + base + lane); v = __ldcs(g_vals + base + lane); }
        for (int k = 0; k < cnt; k++) {
            int   sk = __shfl_sync(0xffffffffu, s, k);
            float vk = __shfl_sync(0xffffffffu, v, k);
            const uint4* hp = (const uint4*)(H + (size_t)sk * DIM);
            uint4 q0 = hp[lane];
            uint4 q1 = hp[lane + 32];
            const __half2* h0 = (const __half2*)&q0;
            const __half2* h1 = (const __half2*)&q1;
#pragma unroll
            for (int j = 0; j < 4; j++) {
                float2 f0 = __half22float2(h0[j]);
                float2 f1 = __half22float2(h1[j]);
                A.f[j].x     = fmaf(vk, f0.x, A.f[j].x);
                A.f[j].y     = fmaf(vk, f0.y, A.f[j].y);
                A.f[j + 4].x = fmaf(vk, f1.x, A.f[j + 4].x);
                A.f[j + 4].y = fmaf(vk, f1.y, A.f[j + 4].y);
            }
        }
    }
#pragma unroll
    for (int j = 0; j < 8; j++) {
        A.f[j].x = fmaxf(A.f[j].x, 0.f);
        A.f[j].y = fmaxf(A.f[j].y, 0.f);
    }
}

// layer-1: gather fp16 -> relu -> fp16 (gemm2 input; plain stores keep it in L2)
__global__ __launch_bounds__(256) void spmm_h16_kernel(const __half* __restrict__ H,
                                                       __half* __restrict__ outh) {
    int row  = (blockIdx.x * blockDim.x + threadIdx.x) >> 5;
    int lane = threadIdx.x & 31;
    if (row >= N_NODES) return;
    Acc16 A;
    gather_row_h(H, g_row_ptr[row], g_row_ptr[row + 1], lane, A);
    __half* op = outh + (size_t)row * DIM;
#pragma unroll
    for (int half = 0; half < 2; half++) {
        uint4 pk;
        __half2 p0 = __floats2half2_rn(A.f[half * 4 + 0].x, A.f[half * 4 + 0].y);
        __half2 p1 = __floats2half2_rn(A.f[half * 4 + 1].x, A.f[half * 4 + 1].y);
        __half2 p2 = __floats2half2_rn(A.f[half * 4 + 2].x, A.f[half * 4 + 2].y);
        __half2 p3 = __floats2half2_rn(A.f[half * 4 + 3].x, A.f[half * 4 + 3].y);
        pk.x = *(uint32_t*)&p0; pk.y = *(uint32_t*)&p1;
        pk.z = *(uint32_t*)&p2; pk.w = *(uint32_t*)&p3;
        *((uint4*)(op + (lane + half * 32) * 8)) = pk;
    }
}

// layer-2: gather fp16 -> relu -> fp32 final output (streamed out)
__global__ __launch_bounds__(256) void spmm_out_kernel(const __half* __restrict__ H,
                                                       float* __restrict__ out) {
    int row  = (blockIdx.x * blockDim.x + threadIdx.x) >> 5;
    int lane = threadIdx.x & 31;
    if (row >= N_NODES) return;
    Acc16 A;
    gather_row_h(H, g_row_ptr[row], g_row_ptr[row + 1], lane, A);
    float* op = out + (size_t)row * DIM;
#pragma unroll
    for (int half = 0; half < 2; half++) {
        float* p = op + (lane + half * 32) * 8;
        float4 v0 = make_float4(A.f[half * 4 + 0].x, A.f[half * 4 + 0].y,
                                A.f[half * 4 + 1].x, A.f[half * 4 + 1].y);
        float4 v1 = make_float4(A.f[half * 4 + 2].x, A.f[half * 4 + 2].y,
                                A.f[half * 4 + 3].x, A.f[half * 4 + 3].y);
        __stcs((float4*)p, v0);
        __stcs((float4*)(p + 4), v1);
    }
}

// ---------------- launcher ----------------------------------------------------
extern "C" void kernel_launch(void* const* d_in, const int* in_sizes, int n_in,
                              void* d_out, int out_size)
{
    const float* x    = (const float*)d_in[0];
    const int*   asrc = (const int*)  d_in[1];
    const int*   adst = (const int*)  d_in[2];
    const float* aval = (const float*)d_in[3];
    const float* W1   = (const float*)d_in[4];
    const float* b1   = (const float*)d_in[5];
    const float* W2   = (const float*)d_in[6];
    const float* b2   = (const float*)d_in[7];
    float* out = (float*)d_out;

    __half *x16, *o16, *h16, *w1t, *w2t;
    cudaGetSymbolAddress((void**)&x16, g_x16);
    cudaGetSymbolAddress((void**)&o16, g_o16);
    cudaGetSymbolAddress((void**)&h16, g_h16);
    cudaGetSymbolAddress((void**)&w1t, g_w1t);
    cudaGetSymbolAddress((void**)&w2t, g_w2t);

    cudaFuncSetAttribute(gemm_f16_kernel, cudaFuncAttributeMaxDynamicSharedMemorySize,
                         GEMM_SMEM);

    // 1) zero degree counters (must precede hist)
    zero_counts_kernel<<<(N_NODES + 255) / 256, 256>>>();
    // 2) merged prep: x->fp16 || degree histogram || W1/W2 transpose->fp16
    prep_kernel<<<NB_PREP, 256>>>(x, adst, W1, W2);
    // 3) prefix-sum -> row_ptr (counts reset for scatter)
    scan_kernel<<<1, 1024>>>();
    // 4) gemm1 with leading scatter blocks (profiled slot idx 3)
    dim3 g1(DIM / 128, SCAT_Y + M_PAD / 256);
    gemm_f16_kernel<<<g1, 512, GEMM_SMEM>>>(x16, w1t, b1, o16, SCAT_Y, asrc, adst, aval);
    // 5) layer-1 aggregate: fp16 gather -> fp16 h1
    spmm_h16_kernel<<<(N_NODES + 7) / 8, 256>>>(o16, h16);
    // 6) gemm2 (no scatter blocks)
    dim3 g2(DIM / 128, M_PAD / 256);
    gemm_f16_kernel<<<g2, 512, GEMM_SMEM>>>(h16, w2t, b2, o16, 0, nullptr, nullptr, nullptr);
    // 7) layer-2 aggregate -> fp32 out
    spmm_out_kernel<<<(N_NODES + 7) / 8, 256>>>(o16, out);
}

// round 16
// speedup vs baseline: 1.1051x; 1.1051x over previous
#include <cuda_runtime.h>
#include <cuda_fp16.h>
#include <cstdint>
#include <cstddef>

#define N_NODES 100000
#define M_PAD   100096            // 782 * 128
#define N_EDGES 3200000
#define DIM 512

// ---------------- scratch (device globals; no runtime allocation) ----------
__device__ __half g_x16[(size_t)M_PAD * DIM];    // fp16(x)
__device__ __half g_o16[(size_t)M_PAD * DIM];    // gemm outputs (both layers)
__device__ __half g_h16[(size_t)M_PAD * DIM];    // spmm1 output (gemm2 input); pad rows stay 0
__device__ __half g_w1t[DIM * DIM];
__device__ __half g_w2t[DIM * DIM];
__device__ int   g_row_ptr[N_NODES + 1];
__device__ int   g_counts[N_NODES];              // protocol: 0 -> degree (hist) -> 0 (scatter)
__device__ int   g_srcs[N_EDGES];
__device__ float g_vals[N_EDGES];

// ---------------- PTX helpers ----------------------------------------------
__device__ __forceinline__ uint32_t smem_u32(const void* p) {
    uint32_t a;
    asm("{ .reg .u64 t; cvta.to.shared.u64 t, %1; cvt.u32.u64 %0, t; }" : "=r"(a) : "l"(p));
    return a;
}

#define CP_ASYNC16(smaddr, gptr) \
    asm volatile("cp.async.cg.shared.global [%0], [%1], 16;" :: "r"(smaddr), "l"(gptr))
#define CP_COMMIT() asm volatile("cp.async.commit_group;" ::: "memory")
#define CP_WAIT(N)  asm volatile("cp.async.wait_group %0;" :: "n"(N) : "memory")

#define LDSM4(R0, R1, R2, R3, addr) \
    asm volatile("ldmatrix.sync.aligned.m8n8.x4.shared.b16 {%0,%1,%2,%3}, [%4];" \
                 : "=r"(R0), "=r"(R1), "=r"(R2), "=r"(R3) : "r"(addr))

#define MMA16816F(C, A, B0, B1) \
    asm volatile("mma.sync.aligned.m16n8k16.row.col.f32.f16.f16.f32 " \
                 "{%0,%1,%2,%3}, {%4,%5,%6,%7}, {%8,%9}, {%0,%1,%2,%3};" \
                 : "+f"((C)[0]), "+f"((C)[1]), "+f"((C)[2]), "+f"((C)[3]) \
                 : "r"((A)[0]), "r"((A)[1]), "r"((A)[2]), "r"((A)[3]), \
                   "r"(B0), "r"(B1))

// ---------------- CSR pieces ------------------------------------------------
// scan: row_ptr from counts; counts KEPT at degree (scatter will decrement to 0)
__global__ __launch_bounds__(1024) void scan_kernel() {
    __shared__ int partials[1024];
    int tid = threadIdx.x;
    const int CHUNK = (N_NODES + 1023) / 1024;
    int b = tid * CHUNK;
    int e = b + CHUNK; if (e > N_NODES) e = N_NODES;
    if (b > N_NODES) b = N_NODES;
    int sum = 0;
    for (int i = b; i < e; i++) sum += g_counts[i];
    partials[tid] = sum;
    __syncthreads();
    for (int off = 1; off < 1024; off <<= 1) {
        int t = (tid >= off) ? partials[tid - off] : 0;
        __syncthreads();
        partials[tid] += t;
        __syncthreads();
    }
    int run = partials[tid] - sum;
    for (int i = b; i < e; i++) {
        g_row_ptr[i] = run;
        run += g_counts[i];
    }
    if (tid == 1023) g_row_ptr[N_NODES] = partials[1023];
}

// ---------------- merged prep: convert_x || hist || W transposes -------------
#define NB_CONV 12512     // 12512 blocks * 1024 float4 = M_PAD*DIM/4
#define NB_HIST 1568
#define NB_W    1024      // 1024 blocks * 256 = DIM*DIM
#define NB_PREP (NB_CONV + NB_HIST + 2 * NB_W)

__global__ __launch_bounds__(256) void prep_kernel(
    const float* __restrict__ x, const int* __restrict__ dst,
    const float* __restrict__ W1, const float* __restrict__ W2)
{
    int b = blockIdx.x;
    if (b < NB_CONV) {
#pragma unroll
        for (int j = 0; j < 4; j++) {
            size_t i = (size_t)b * 1024 + j * 256 + threadIdx.x;
            size_t row = i / (DIM / 4);
            float4 v = make_float4(0.f, 0.f, 0.f, 0.f);
            if (row < N_NODES) v = ((const float4*)x)[i];
            __half2 h0 = __floats2half2_rn(v.x, v.y);
            __half2 h1 = __floats2half2_rn(v.z, v.w);
            uint2 pk;
            pk.x = *(uint32_t*)&h0;
            pk.y = *(uint32_t*)&h1;
            ((uint2*)g_x16)[i] = pk;
        }
    } else if (b < NB_CONV + NB_HIST) {
        int gtid = (b - NB_CONV) * 256 + threadIdx.x;
        const int stride = NB_HIST * 256;
        for (int e = gtid; e < N_EDGES; e += stride)
            atomicAdd(&g_counts[__ldcs(dst + e)], 1);
    } else {
        int b3 = b - NB_CONV - NB_HIST;
        const float* W = (b3 < NB_W) ? W1 : W2;
        __half* Wt = (b3 < NB_W) ? g_w1t : g_w2t;
        int idx = (b3 & (NB_W - 1)) * 256 + threadIdx.x;
        int k = idx >> 9, n = idx & 511;
        Wt[n * DIM + k] = __float2half_rn(W[idx]);
    }
}

// ---------------- HMMA fp16 GEMM, 3-stage single-sync pipeline ---------------
// C[.,512](fp16) = A(fp16) @ Wt^T + bias, fp32 accum.
// CTA 128x128, 8 warps (warp 64x32), K-chunk 32, 3-stage cp.async pipeline.
// Leading extraY block-rows perform the CSR scatter (gemm1 only);
// at 2 CTA/SM scatter CTAs co-reside with gemm CTAs -> nearly free.
#define BK 32
#define ROWB 80
#define OFF_A   0
#define OFF_B   10240
#define STAGE_BYTES 20480
#define NSTAGE 3
#define GEMM_SMEM (NSTAGE * STAGE_BYTES)
#define NIT (DIM / BK)               // 16
#define SCAT_Y 64                    // 64*4 blocks * 256 thr = 65536 scatter threads

__device__ __forceinline__ void stage_load(
    uint32_t sbase, int stage,
    const __half* __restrict__ A, const __half* __restrict__ B,
    int m0, int n0, int k0, int tid)
{
    uint32_t s0 = sbase + (uint32_t)stage * STAGE_BYTES;
#pragma unroll
    for (int i = tid; i < 512; i += 256) {
        int r = i >> 2, s = i & 3;
        uint32_t so = (uint32_t)r * ROWB + (uint32_t)s * 16u;
        const char* ga = (const char*)(A + (size_t)(m0 + r) * DIM + k0) + s * 16;
        const char* gb = (const char*)(B + (size_t)(n0 + r) * DIM + k0) + s * 16;
        CP_ASYNC16(s0 + OFF_A + so, ga);
        CP_ASYNC16(s0 + OFF_B + so, gb);
    }
}

__global__ __launch_bounds__(256, 2) void gemm_f16_kernel(
    const __half* __restrict__ A, const __half* __restrict__ B,
    const float* __restrict__ bias, __half* __restrict__ C,
    int extraY,
    const int* __restrict__ esrc, const int* __restrict__ edst,
    const float* __restrict__ eval)
{
    if ((int)blockIdx.y < extraY) {
        // CSR scatter (back-to-front via decrement; counts end at 0 for next run)
        int t0 = blockIdx.y * gridDim.x + blockIdx.x;          // 0..255
        int gtid = t0 * 256 + threadIdx.x;
        const int stride = SCAT_Y * 4 * 256;                   // 65536
        for (int e = gtid; e < N_EDGES; e += stride) {
            int d = __ldcs(edst + e);
            int pos = g_row_ptr[d] + atomicSub(&g_counts[d], 1) - 1;
            g_srcs[pos] = __ldcs(esrc + e);
            g_vals[pos] = __ldcs(eval + e);
        }
        return;
    }

    extern __shared__ char sm[];
    const uint32_t sbase = smem_u32(sm);
    const int tid  = threadIdx.x;
    const int warp = tid >> 5;
    const int lane = tid & 31;
    const int wm = warp & 1;
    const int wn = warp >> 1;
    const int n0 = blockIdx.x * 128;              // n fastest -> wave shares A rows
    const int m0 = (blockIdx.y - extraY) * 128;

    float acc[4][4][4];
#pragma unroll
    for (int a = 0; a < 4; a++)
#pragma unroll
        for (int b = 0; b < 4; b++)
#pragma unroll
            for (int c = 0; c < 4; c++) acc[a][b][c] = 0.f;

    const int a_row = lane & 15;
    const int a_koff = (lane >> 4) * 8;
    const int b_g = lane >> 3;
    const int b_nloc = ((b_g >> 1) << 3) + (lane & 7);
    const int b_koff = (b_g & 1) * 8;

    // prime stages 0 and 1
    stage_load(sbase, 0, A, B, m0, n0, 0, tid);
    CP_COMMIT();
    stage_load(sbase, 1, A, B, m0, n0, BK, tid);
    CP_COMMIT();

    int stg = 0;                  // stage index of iteration `it` (mod NSTAGE)
    for (int it = 0; it < NIT; ++it) {
        if (it + 1 < NIT) { CP_WAIT(1); } else { CP_WAIT(0); }
        __syncthreads();          // stage `stg` ready; all warps done with stage (stg+2)%3

        if (it + 2 < NIT) {
            int nstg = stg + 2; if (nstg >= NSTAGE) nstg -= NSTAGE;
            stage_load(sbase, nstg, A, B, m0, n0, (it + 2) * BK, tid);
            CP_COMMIT();
        }

        const uint32_t st = sbase + (uint32_t)stg * STAGE_BYTES;
#pragma unroll
        for (int kk = 0; kk < 2; ++kk) {
            const int k16 = kk * 16;
            uint32_t av[4][4];
#pragma unroll
            for (int mi = 0; mi < 4; ++mi) {
                uint32_t ra = (uint32_t)(wm * 64 + mi * 16 + a_row) * ROWB
                            + (uint32_t)(k16 + a_koff) * 2;
                LDSM4(av[mi][0], av[mi][1], av[mi][2], av[mi][3], st + OFF_A + ra);
            }
            uint32_t bv[2][4];
#pragma unroll
            for (int nb = 0; nb < 2; ++nb) {
                uint32_t rb = (uint32_t)(wn * 32 + nb * 16 + b_nloc) * ROWB
                            + (uint32_t)(k16 + b_koff) * 2;
                LDSM4(bv[nb][0], bv[nb][1], bv[nb][2], bv[nb][3], st + OFF_B + rb);
            }
#pragma unroll
            for (int mi = 0; mi < 4; ++mi) {
#pragma unroll
                for (int j = 0; j < 4; ++j) {
                    const int nb = j >> 1, blk = j & 1;
                    MMA16816F(acc[mi][j], av[mi], bv[nb][blk * 2], bv[nb][blk * 2 + 1]);
                }
            }
        }
        if (++stg >= NSTAGE) stg = 0;
    }

    // epilogue: bias add + fp16 store (plain stores -> lands in L2 for SpMM)
#pragma unroll
    for (int mi = 0; mi < 4; ++mi) {
        int row = m0 + wm * 64 + mi * 16 + (lane >> 2);
#pragma unroll
        for (int j = 0; j < 4; ++j) {
            int col = n0 + wn * 32 + j * 8 + (lane & 3) * 2;
            float b0 = bias[col], b1 = bias[col + 1];
            __half2 v0 = __floats2half2_rn(acc[mi][j][0] + b0, acc[mi][j][1] + b1);
            __half2 v1 = __floats2half2_rn(acc[mi][j][2] + b0, acc[mi][j][3] + b1);
            *(__half2*)(C + (size_t)row * DIM + col) = v0;
            *(__half2*)(C + (size_t)(row + 8) * DIM + col) = v1;
        }
    }
}

// ---------------- SpMM (CSR by dst), fp16 gather, one warp per row -----------
struct Acc16 { float2 f[8]; };

__device__ __forceinline__ void gather_row_h(const __half* __restrict__ H,
                                             int beg, int end, int lane, Acc16& A) {
#pragma unroll
    for (int j = 0; j < 8; j++) A.f[j] = make_float2(0.f, 0.f);
    for (int base = beg; base < end; base += 32) {
        int cnt = end - base; if (cnt > 32) cnt = 32;
        int s = 0; float v = 0.f;
        if (lane < cnt) { s = __ldcs(g_srcs + base + lane); v = __ldcs(g_vals + base + lane); }
        for (int k = 0; k < cnt; k++) {
            int   sk = __shfl_sync(0xffffffffu, s, k);
            float vk = __shfl_sync(0xffffffffu, v, k);
            const uint4* hp = (const uint4*)(H + (size_t)sk * DIM);
            uint4 q0 = hp[lane];
            uint4 q1 = hp[lane + 32];
            const __half2* h0 = (const __half2*)&q0;
            const __half2* h1 = (const __half2*)&q1;
#pragma unroll
            for (int j = 0; j < 4; j++) {
                float2 f0 = __half22float2(h0[j]);
                float2 f1 = __half22float2(h1[j]);
                A.f[j].x     = fmaf(vk, f0.x, A.f[j].x);
                A.f[j].y     = fmaf(vk, f0.y, A.f[j].y);
                A.f[j + 4].x = fmaf(vk, f1.x, A.f[j + 4].x);
                A.f[j + 4].y = fmaf(vk, f1.y, A.f[j + 4].y);
            }
        }
    }
#pragma unroll
    for (int j = 0; j < 8; j++) {
        A.f[j].x = fmaxf(A.f[j].x, 0.f);
        A.f[j].y = fmaxf(A.f[j].y, 0.f);
    }
}

// layer-1: gather fp16 -> relu -> fp16 (gemm2 input; plain stores keep it in L2)
__global__ __launch_bounds__(256) void spmm_h16_kernel(const __half* __restrict__ H,
                                                       __half* __restrict__ outh) {
    int row  = (blockIdx.x * blockDim.x + threadIdx.x) >> 5;
    int lane = threadIdx.x & 31;
    if (row >= N_NODES) return;
    Acc16 A;
    gather_row_h(H, g_row_ptr[row], g_row_ptr[row + 1], lane, A);
    __half* op = outh + (size_t)row * DIM;
#pragma unroll
    for (int half = 0; half < 2; half++) {
        uint4 pk;
        __half2 p0 = __floats2half2_rn(A.f[half * 4 + 0].x, A.f[half * 4 + 0].y);
        __half2 p1 = __floats2half2_rn(A.f[half * 4 + 1].x, A.f[half * 4 + 1].y);
        __half2 p2 = __floats2half2_rn(A.f[half * 4 + 2].x, A.f[half * 4 + 2].y);
        __half2 p3 = __floats2half2_rn(A.f[half * 4 + 3].x, A.f[half * 4 + 3].y);
        pk.x = *(uint32_t*)&p0; pk.y = *(uint32_t*)&p1;
        pk.z = *(uint32_t*)&p2; pk.w = *(uint32_t*)&p3;
        *((uint4*)(op + (lane + half * 32) * 8)) = pk;
    }
}

// layer-2: gather fp16 -> relu -> fp32 final output (streamed out)
__global__ __launch_bounds__(256) void spmm_out_kernel(const __half* __restrict__ H,
                                                       float* __restrict__ out) {
    int row  = (blockIdx.x * blockDim.x + threadIdx.x) >> 5;
    int lane = threadIdx.x & 31;
    if (row >= N_NODES) return;
    Acc16 A;
    gather_row_h(H, g_row_ptr[row], g_row_ptr[row + 1], lane, A);
    float* op = out + (size_t)row * DIM;
#pragma unroll
    for (int half = 0; half < 2; half++) {
        float* p = op + (lane + half * 32) * 8;
        float4 v0 = make_float4(A.f[half * 4 + 0].x, A.f[half * 4 + 0].y,
                                A.f[half * 4 + 1].x, A.f[half * 4 + 1].y);
        float4 v1 = make_float4(A.f[half * 4 + 2].x, A.f[half * 4 + 2].y,
                                A.f[half * 4 + 3].x, A.f[half * 4 + 3].y);
        __stcs((float4*)p, v0);
        __stcs((float4*)(p + 4), v1);
    }
}

// ---------------- launcher ----------------------------------------------------
extern "C" void kernel_launch(void* const* d_in, const int* in_sizes, int n_in,
                              void* d_out, int out_size)
{
    const float* x    = (const float*)d_in[0];
    const int*   asrc = (const int*)  d_in[1];
    const int*   adst = (const int*)  d_in[2];
    const float* aval = (const float*)d_in[3];
    const float* W1   = (const float*)d_in[4];
    const float* b1   = (const float*)d_in[5];
    const float* W2   = (const float*)d_in[6];
    const float* b2   = (const float*)d_in[7];
    float* out = (float*)d_out;

    __half *x16, *o16, *h16, *w1t, *w2t;
    cudaGetSymbolAddress((void**)&x16, g_x16);
    cudaGetSymbolAddress((void**)&o16, g_o16);
    cudaGetSymbolAddress((void**)&h16, g_h16);
    cudaGetSymbolAddress((void**)&w1t, g_w1t);
    cudaGetSymbolAddress((void**)&w2t, g_w2t);

    cudaFuncSetAttribute(gemm_f16_kernel, cudaFuncAttributeMaxDynamicSharedMemorySize,
                         GEMM_SMEM);

    // 1) merged prep: x->fp16 || degree histogram (counts 0->degree) || W transposes
    prep_kernel<<<NB_PREP, 256>>>(x, adst, W1, W2);
    // 2) prefix-sum -> row_ptr (counts stay at degree; scatter returns them to 0)
    scan_kernel<<<1, 1024>>>();
    // 3) gemm1 with leading scatter blocks (profiled slot idx 3 is gemm1... now idx 2)
    dim3 g1(DIM / 128, SCAT_Y + M_PAD / 128);
    gemm_f16_kernel<<<g1, 256, GEMM_SMEM>>>(x16, w1t, b1, o16, SCAT_Y, asrc, adst, aval);
    // 4) layer-1 aggregate: fp16 gather -> fp16 h1
    spmm_h16_kernel<<<(N_NODES + 7) / 8, 256>>>(o16, h16);
    // 5) gemm2 (no scatter blocks)
    dim3 g2(DIM / 128, M_PAD / 128);
    gemm_f16_kernel<<<g2, 256, GEMM_SMEM>>>(h16, w2t, b2, o16, 0, nullptr, nullptr, nullptr);
    // 6) layer-2 aggregate -> fp32 out
    spmm_out_kernel<<<(N_NODES + 7) / 8, 256>>>(o16, out);
}

// round 17
// speedup vs baseline: 1.1294x; 1.0220x over previous
#include <cuda_runtime.h>
#include <cuda_fp16.h>
#include <cstdint>
#include <cstddef>

#define N_NODES 100000
#define M_PAD   100096            // 782 * 128
#define N_EDGES 3200000
#define DIM 512

// ---------------- scratch (device globals; no runtime allocation) ----------
__device__ __half g_x16[(size_t)M_PAD * DIM];    // fp16(x)
__device__ __half g_o16[(size_t)M_PAD * DIM];    // gemm outputs (both layers)
__device__ __half g_h16[(size_t)M_PAD * DIM];    // spmm1 output (gemm2 input); pad rows stay 0
__device__ __half g_w1t[DIM * DIM];
__device__ __half g_w2t[DIM * DIM];
__device__ int   g_row_ptr[N_NODES + 1];
__device__ int   g_counts[N_NODES];              // protocol: 0 -> degree (hist) -> 0 (scatter)
__device__ int   g_srcs[N_EDGES];
__device__ float g_vals[N_EDGES];

// ---------------- PTX helpers ----------------------------------------------
__device__ __forceinline__ uint32_t smem_u32(const void* p) {
    uint32_t a;
    asm("{ .reg .u64 t; cvta.to.shared.u64 t, %1; cvt.u32.u64 %0, t; }" : "=r"(a) : "l"(p));
    return a;
}

#define CP_ASYNC16(smaddr, gptr) \
    asm volatile("cp.async.cg.shared.global [%0], [%1], 16;" :: "r"(smaddr), "l"(gptr))
#define CP_COMMIT() asm volatile("cp.async.commit_group;" ::: "memory")
#define CP_WAIT(N)  asm volatile("cp.async.wait_group %0;" :: "n"(N) : "memory")

#define LDSM4(R0, R1, R2, R3, addr) \
    asm volatile("ldmatrix.sync.aligned.m8n8.x4.shared.b16 {%0,%1,%2,%3}, [%4];" \
                 : "=r"(R0), "=r"(R1), "=r"(R2), "=r"(R3) : "r"(addr))

#define MMA16816F(C, A, B0, B1) \
    asm volatile("mma.sync.aligned.m16n8k16.row.col.f32.f16.f16.f32 " \
                 "{%0,%1,%2,%3}, {%4,%5,%6,%7}, {%8,%9}, {%0,%1,%2,%3};" \
                 : "+f"((C)[0]), "+f"((C)[1]), "+f"((C)[2]), "+f"((C)[3]) \
                 : "r"((A)[0]), "r"((A)[1]), "r"((A)[2]), "r"((A)[3]), \
                   "r"(B0), "r"(B1))

// ---------------- CSR pieces ------------------------------------------------
// scan: row_ptr from counts; counts KEPT at degree (scatter will decrement to 0)
__global__ __launch_bounds__(1024) void scan_kernel() {
    __shared__ int partials[1024];
    int tid = threadIdx.x;
    const int CHUNK = (N_NODES + 1023) / 1024;
    int b = tid * CHUNK;
    int e = b + CHUNK; if (e > N_NODES) e = N_NODES;
    if (b > N_NODES) b = N_NODES;
    int sum = 0;
    for (int i = b; i < e; i++) sum += g_counts[i];
    partials[tid] = sum;
    __syncthreads();
    for (int off = 1; off < 1024; off <<= 1) {
        int t = (tid >= off) ? partials[tid - off] : 0;
        __syncthreads();
        partials[tid] += t;
        __syncthreads();
    }
    int run = partials[tid] - sum;
    for (int i = b; i < e; i++) {
        g_row_ptr[i] = run;
        run += g_counts[i];
    }
    if (tid == 1023) g_row_ptr[N_NODES] = partials[1023];
}

// ---------------- merged prep: convert_x || hist || W transposes -------------
#define NB_CONV 12512     // 12512 blocks * 1024 float4 = M_PAD*DIM/4
#define NB_HIST 1568
#define NB_W    1024      // 1024 blocks * 256 = DIM*DIM
#define NB_PREP (NB_CONV + NB_HIST + 2 * NB_W)

__global__ __launch_bounds__(256) void prep_kernel(
    const float* __restrict__ x, const int* __restrict__ dst,
    const float* __restrict__ W1, const float* __restrict__ W2)
{
    int b = blockIdx.x;
    if (b < NB_CONV) {
#pragma unroll
        for (int j = 0; j < 4; j++) {
            size_t i = (size_t)b * 1024 + j * 256 + threadIdx.x;
            size_t row = i / (DIM / 4);
            float4 v = make_float4(0.f, 0.f, 0.f, 0.f);
            if (row < N_NODES) v = ((const float4*)x)[i];
            __half2 h0 = __floats2half2_rn(v.x, v.y);
            __half2 h1 = __floats2half2_rn(v.z, v.w);
            uint2 pk;
            pk.x = *(uint32_t*)&h0;
            pk.y = *(uint32_t*)&h1;
            ((uint2*)g_x16)[i] = pk;
        }
    } else if (b < NB_CONV + NB_HIST) {
        int gtid = (b - NB_CONV) * 256 + threadIdx.x;
        const int stride = NB_HIST * 256;
        for (int e = gtid; e < N_EDGES; e += stride)
            atomicAdd(&g_counts[__ldcs(dst + e)], 1);
    } else {
        int b3 = b - NB_CONV - NB_HIST;
        const float* W = (b3 < NB_W) ? W1 : W2;
        __half* Wt = (b3 < NB_W) ? g_w1t : g_w2t;
        int idx = (b3 & (NB_W - 1)) * 256 + threadIdx.x;
        int k = idx >> 9, n = idx & 511;
        Wt[n * DIM + k] = __float2half_rn(W[idx]);
    }
}

// ---------------- HMMA fp16 GEMM, 3-stage single-sync pipeline ---------------
// C[.,512](fp16) = A(fp16) @ Wt^T + bias, fp32 accum.
// CTA 128x128, 8 warps (warp 64x32), K-chunk 32, 3-stage cp.async pipeline.
// Leading extraY block-rows perform the CSR scatter (gemm1 only);
// at 2 CTA/SM scatter CTAs co-reside with gemm CTAs.
#define BK 32
#define ROWB 80
#define OFF_A   0
#define OFF_B   10240
#define STAGE_BYTES 20480
#define NSTAGE 3
#define GEMM_SMEM (NSTAGE * STAGE_BYTES)
#define NIT (DIM / BK)               // 16
#define SCAT_Y 64                    // 64*4 blocks * 256 thr = 65536 scatter threads

__device__ __forceinline__ void stage_load(
    uint32_t sbase, int stage,
    const __half* __restrict__ A, const __half* __restrict__ B,
    int m0, int n0, int k0, int tid)
{
    uint32_t s0 = sbase + (uint32_t)stage * STAGE_BYTES;
#pragma unroll
    for (int i = tid; i < 512; i += 256) {
        int r = i >> 2, s = i & 3;
        uint32_t so = (uint32_t)r * ROWB + (uint32_t)s * 16u;
        const char* ga = (const char*)(A + (size_t)(m0 + r) * DIM + k0) + s * 16;
        const char* gb = (const char*)(B + (size_t)(n0 + r) * DIM + k0) + s * 16;
        CP_ASYNC16(s0 + OFF_A + so, ga);
        CP_ASYNC16(s0 + OFF_B + so, gb);
    }
}

__global__ __launch_bounds__(256, 2) void gemm_f16_kernel(
    const __half* __restrict__ A, const __half* __restrict__ B,
    const float* __restrict__ bias, __half* __restrict__ C,
    int extraY,
    const int* __restrict__ esrc, const int* __restrict__ edst,
    const float* __restrict__ eval)
{
    if ((int)blockIdx.y < extraY) {
        // CSR scatter (back-to-front via decrement; counts end at 0 for next run)
        int t0 = blockIdx.y * gridDim.x + blockIdx.x;          // 0..255
        int gtid = t0 * 256 + threadIdx.x;
        const int stride = SCAT_Y * 4 * 256;                   // 65536
        for (int e = gtid; e < N_EDGES; e += stride) {
            int d = __ldcs(edst + e);
            int pos = g_row_ptr[d] + atomicSub(&g_counts[d], 1) - 1;
            g_srcs[pos] = __ldcs(esrc + e);
            g_vals[pos] = __ldcs(eval + e);
        }
        return;
    }

    extern __shared__ char sm[];
    const uint32_t sbase = smem_u32(sm);
    const int tid  = threadIdx.x;
    const int warp = tid >> 5;
    const int lane = tid & 31;
    const int wm = warp & 1;
    const int wn = warp >> 1;
    const int n0 = blockIdx.x * 128;              // n fastest -> wave shares A rows
    const int m0 = (blockIdx.y - extraY) * 128;

    float acc[4][4][4];
#pragma unroll
    for (int a = 0; a < 4; a++)
#pragma unroll
        for (int b = 0; b < 4; b++)
#pragma unroll
            for (int c = 0; c < 4; c++) acc[a][b][c] = 0.f;

    const int a_row = lane & 15;
    const int a_koff = (lane >> 4) * 8;
    const int b_g = lane >> 3;
    const int b_nloc = ((b_g >> 1) << 3) + (lane & 7);
    const int b_koff = (b_g & 1) * 8;

    // prime stages 0 and 1
    stage_load(sbase, 0, A, B, m0, n0, 0, tid);
    CP_COMMIT();
    stage_load(sbase, 1, A, B, m0, n0, BK, tid);
    CP_COMMIT();

    int stg = 0;                  // stage index of iteration `it` (mod NSTAGE)
    for (int it = 0; it < NIT; ++it) {
        if (it + 1 < NIT) { CP_WAIT(1); } else { CP_WAIT(0); }
        __syncthreads();          // stage `stg` ready; all warps done with stage (stg+2)%3

        if (it + 2 < NIT) {
            int nstg = stg + 2; if (nstg >= NSTAGE) nstg -= NSTAGE;
            stage_load(sbase, nstg, A, B, m0, n0, (it + 2) * BK, tid);
            CP_COMMIT();
        }

        const uint32_t st = sbase + (uint32_t)stg * STAGE_BYTES;
#pragma unroll
        for (int kk = 0; kk < 2; ++kk) {
            const int k16 = kk * 16;
            uint32_t av[4][4];
#pragma unroll
            for (int mi = 0; mi < 4; ++mi) {
                uint32_t ra = (uint32_t)(wm * 64 + mi * 16 + a_row) * ROWB
                            + (uint32_t)(k16 + a_koff) * 2;
                LDSM4(av[mi][0], av[mi][1], av[mi][2], av[mi][3], st + OFF_A + ra);
            }
            uint32_t bv[2][4];
#pragma unroll
            for (int nb = 0; nb < 2; ++nb) {
                uint32_t rb = (uint32_t)(wn * 32 + nb * 16 + b_nloc) * ROWB
                            + (uint32_t)(k16 + b_koff) * 2;
                LDSM4(bv[nb][0], bv[nb][1], bv[nb][2], bv[nb][3], st + OFF_B + rb);
            }
#pragma unroll
            for (int mi = 0; mi < 4; ++mi) {
#pragma unroll
                for (int j = 0; j < 4; ++j) {
                    const int nb = j >> 1, blk = j & 1;
                    MMA16816F(acc[mi][j], av[mi], bv[nb][blk * 2], bv[nb][blk * 2 + 1]);
                }
            }
        }
        if (++stg >= NSTAGE) stg = 0;
    }

    // epilogue: bias add + fp16 store (plain stores -> lands in L2 for SpMM)
#pragma unroll
    for (int mi = 0; mi < 4; ++mi) {
        int row = m0 + wm * 64 + mi * 16 + (lane >> 2);
#pragma unroll
        for (int j = 0; j < 4; ++j) {
            int col = n0 + wn * 32 + j * 8 + (lane & 3) * 2;
            float b0 = bias[col], b1 = bias[col + 1];
            __half2 v0 = __floats2half2_rn(acc[mi][j][0] + b0, acc[mi][j][1] + b1);
            __half2 v1 = __floats2half2_rn(acc[mi][j][2] + b0, acc[mi][j][3] + b1);
            *(__half2*)(C + (size_t)row * DIM + col) = v0;
            *(__half2*)(C + (size_t)(row + 8) * DIM + col) = v1;
        }
    }
}

// ---------------- SpMM (CSR by dst), fp16 gather, TWO warps per row ----------
// Warp handles a 256-dim half-row: lane owns dims [half*256 + lane*8, +8).
// Half the registers of the 1-warp version -> 6 CTA/SM -> ~75% occupancy.

__device__ __forceinline__ void gather_half_row(const __half* __restrict__ H,
                                                int beg, int end, int lane, int halfSel,
                                                float2 f[4]) {
#pragma unroll
    for (int j = 0; j < 4; j++) f[j] = make_float2(0.f, 0.f);
    const int qoff = halfSel * 32 + lane;     // uint4 index within row
    for (int base = beg; base < end; base += 32) {
        int cnt = end - base; if (cnt > 32) cnt = 32;
        int s = 0; float v = 0.f;
        if (lane < cnt) { s = __ldcs(g_srcs + base + lane); v = __ldcs(g_vals + base + lane); }
        for (int k = 0; k < cnt; k++) {
            int   sk = __shfl_sync(0xffffffffu, s, k);
            float vk = __shfl_sync(0xffffffffu, v, k);
            uint4 q = ((const uint4*)(H + (size_t)sk * DIM))[qoff];
            const __half2* h2 = (const __half2*)&q;
#pragma unroll
            for (int j = 0; j < 4; j++) {
                float2 f0 = __half22float2(h2[j]);
                f[j].x = fmaf(vk, f0.x, f[j].x);
                f[j].y = fmaf(vk, f0.y, f[j].y);
            }
        }
    }
#pragma unroll
    for (int j = 0; j < 4; j++) {
        f[j].x = fmaxf(f[j].x, 0.f);
        f[j].y = fmaxf(f[j].y, 0.f);
    }
}

// layer-1: gather fp16 -> relu -> fp16 (gemm2 input; plain stores keep it in L2)
__global__ __launch_bounds__(256, 6) void spmm_h16_kernel(const __half* __restrict__ H,
                                                          __half* __restrict__ outh) {
    int gw   = (blockIdx.x * blockDim.x + threadIdx.x) >> 5;   // global warp
    int row  = gw >> 1;
    int halfSel = gw & 1;
    int lane = threadIdx.x & 31;
    if (row >= N_NODES) return;
    float2 f[4];
    gather_half_row(H, g_row_ptr[row], g_row_ptr[row + 1], lane, halfSel, f);
    __half* op = outh + (size_t)row * DIM + halfSel * 256 + lane * 8;
    uint4 pk;
    __half2 p0 = __floats2half2_rn(f[0].x, f[0].y);
    __half2 p1 = __floats2half2_rn(f[1].x, f[1].y);
    __half2 p2 = __floats2half2_rn(f[2].x, f[2].y);
    __half2 p3 = __floats2half2_rn(f[3].x, f[3].y);
    pk.x = *(uint32_t*)&p0; pk.y = *(uint32_t*)&p1;
    pk.z = *(uint32_t*)&p2; pk.w = *(uint32_t*)&p3;
    *((uint4*)op) = pk;
}

// layer-2: gather fp16 -> relu -> fp32 final output (streamed out)
__global__ __launch_bounds__(256, 6) void spmm_out_kernel(const __half* __restrict__ H,
                                                          float* __restrict__ out) {
    int gw   = (blockIdx.x * blockDim.x + threadIdx.x) >> 5;
    int row  = gw >> 1;
    int halfSel = gw & 1;
    int lane = threadIdx.x & 31;
    if (row >= N_NODES) return;
    float2 f[4];
    gather_half_row(H, g_row_ptr[row], g_row_ptr[row + 1], lane, halfSel, f);
    float* p = out + (size_t)row * DIM + halfSel * 256 + lane * 8;
    float4 v0 = make_float4(f[0].x, f[0].y, f[1].x, f[1].y);
    float4 v1 = make_float4(f[2].x, f[2].y, f[3].x, f[3].y);
    __stcs((float4*)p, v0);
    __stcs((float4*)(p + 4), v1);
}

// ---------------- launcher ----------------------------------------------------
extern "C" void kernel_launch(void* const* d_in, const int* in_sizes, int n_in,
                              void* d_out, int out_size)
{
    const float* x    = (const float*)d_in[0];
    const int*   asrc = (const int*)  d_in[1];
    const int*   adst = (const int*)  d_in[2];
    const float* aval = (const float*)d_in[3];
    const float* W1   = (const float*)d_in[4];
    const float* b1   = (const float*)d_in[5];
    const float* W2   = (const float*)d_in[6];
    const float* b2   = (const float*)d_in[7];
    float* out = (float*)d_out;

    __half *x16, *o16, *h16, *w1t, *w2t;
    cudaGetSymbolAddress((void**)&x16, g_x16);
    cudaGetSymbolAddress((void**)&o16, g_o16);
    cudaGetSymbolAddress((void**)&h16, g_h16);
    cudaGetSymbolAddress((void**)&w1t, g_w1t);
    cudaGetSymbolAddress((void**)&w2t, g_w2t);

    cudaFuncSetAttribute(gemm_f16_kernel, cudaFuncAttributeMaxDynamicSharedMemorySize,
                         GEMM_SMEM);

    const int spmm_blocks = (2 * N_NODES + 7) / 8;   // 2 warps per row, 8 warps per block

    // 1) merged prep: x->fp16 || degree histogram (counts 0->degree) || W transposes
    prep_kernel<<<NB_PREP, 256>>>(x, adst, W1, W2);
    // 2) prefix-sum -> row_ptr (counts stay at degree; scatter returns them to 0)
    scan_kernel<<<1, 1024>>>();
    // 3) gemm1 with leading scatter blocks
    dim3 g1(DIM / 128, SCAT_Y + M_PAD / 128);
    gemm_f16_kernel<<<g1, 256, GEMM_SMEM>>>(x16, w1t, b1, o16, SCAT_Y, asrc, adst, aval);
    // 4) layer-1 aggregate: fp16 gather -> fp16 h1
    spmm_h16_kernel<<<spmm_blocks, 256>>>(o16, h16);
    // 5) gemm2 (no scatter blocks)
    dim3 g2(DIM / 128, M_PAD / 128);
    gemm_f16_kernel<<<g2, 256, GEMM_SMEM>>>(h16, w2t, b2, o16, 0, nullptr, nullptr, nullptr);
    // 6) layer-2 aggregate -> fp32 out
    spmm_out_kernel<<<spmm_blocks, 256>>>(o16, out);
}